// round 3
// baseline (speedup 1.0000x reference)
#include <cuda_runtime.h>
#include <cuda_bf16.h>
#include <cstdint>
#include <math.h>

// Problem dims
#define BB 4
#define SS 1024
#define DM 1024
#define NH 16
#define DK 64
#define DV 64

// Scratch for projected Q/K/V in [b, h, s, d] layout
__device__ float g_Q[BB * NH * SS * DK];
__device__ float g_K[BB * NH * SS * DK];
__device__ float g_V[BB * NH * SS * DV];

// ---------------------------------------------------------------------------
// tf32 mma helpers
// ---------------------------------------------------------------------------
__device__ __forceinline__ uint32_t f2tf32(float x) {
    uint32_t r;
    asm("cvt.rna.tf32.f32 %0, %1;" : "=r"(r) : "f"(x));
    return r;
}

__device__ __forceinline__ void mma_tf32(float c[4], const uint32_t a[4], const uint32_t b[2]) {
    asm volatile(
        "mma.sync.aligned.m16n8k8.row.col.f32.tf32.tf32.f32 "
        "{%0,%1,%2,%3}, {%4,%5,%6,%7}, {%8,%9}, {%0,%1,%2,%3};"
        : "+f"(c[0]), "+f"(c[1]), "+f"(c[2]), "+f"(c[3])
        : "r"(a[0]), "r"(a[1]), "r"(a[2]), "r"(a[3]), "r"(b[0]), "r"(b[1]));
}

// ---------------------------------------------------------------------------
// Projection GEMM via tf32 mma.sync with 3xTF32 compensation.
// Y[4096,1024] = X[4096,1024] @ W[1024,1024] + bias, remapped to [b,h,s,d].
// Tiles: 128x128x32. 8 warps = 2(M) x 4(N); each warp 64x32 via 4x4 m16n8 tiles.
// ---------------------------------------------------------------------------
#define ASTR 36   // As row stride (floats): 128 rows x 32 + pad4 -> LDSM conflict-free
#define WSTR 136  // Ws row stride (floats): 32 rows x 128 + pad8 -> B-load conflict-free

__global__ __launch_bounds__(256, 1) void proj_mma_kernel(
    const float* __restrict__ xq, const float* __restrict__ xk, const float* __restrict__ xv,
    const float* __restrict__ wq, const float* __restrict__ wk, const float* __restrict__ wv,
    const float* __restrict__ bq, const float* __restrict__ bk, const float* __restrict__ bv)
{
    __shared__ float As[128 * ASTR];
    __shared__ float Ws[32 * WSTR];

    const float* X; const float* W; const float* bias; float* out;
    int which = blockIdx.z;
    if (which == 0)      { X = xq; W = wq; bias = bq; out = g_Q; }
    else if (which == 1) { X = xk; W = wk; bias = bk; out = g_K; }
    else                 { X = xv; W = wv; bias = bv; out = g_V; }

    const int tid  = threadIdx.x;
    const int warp = tid >> 5;
    const int lane = tid & 31;
    const int wm   = warp >> 2;   // 0..1
    const int wn   = warp & 3;    // 0..3
    const int tileM = blockIdx.y * 128;
    const int tileN = blockIdx.x * 128;

    // ldmatrix per-lane addressing: block i <- threads 8i..8i+7 supply rows.
    // blocks: (m0-7,k0-3),(m8-15,k0-3),(m0-7,k4-7),(m8-15,k4-7)
    const int lrow = (lane & 7) + ((lane >> 3) & 1) * 8;  // row within m16
    const int lkc  = (lane >> 4) * 4;                     // 0 or 4 (float col)
    const int a_lane_off = lrow * ASTR + lkc;

    const uint32_t As_base = (uint32_t)__cvta_generic_to_shared(As);

    float acc[4][4][4];
#pragma unroll
    for (int mt = 0; mt < 4; mt++)
#pragma unroll
        for (int nt = 0; nt < 4; nt++)
#pragma unroll
            for (int i = 0; i < 4; i++) acc[mt][nt][i] = 0.0f;

    float4 xr[4], wr[4];

    // preload chunk 0
#pragma unroll
    for (int p = 0; p < 4; p++) {
        int id = tid + 256 * p;
        xr[p] = *(const float4*)&X[(size_t)(tileM + (id >> 3)) * DM + (id & 7) * 4];
        wr[p] = *(const float4*)&W[(size_t)(id >> 5) * DM + tileN + (id & 31) * 4];
    }

    for (int k0 = 0; k0 < DM; k0 += 32) {
        __syncthreads();
#pragma unroll
        for (int p = 0; p < 4; p++) {
            int id = tid + 256 * p;
            *(float4*)&As[(id >> 3) * ASTR + (id & 7) * 4] = xr[p];
            *(float4*)&Ws[(id >> 5) * WSTR + (id & 31) * 4] = wr[p];
        }
        __syncthreads();

        if (k0 + 32 < DM) {
#pragma unroll
            for (int p = 0; p < 4; p++) {
                int id = tid + 256 * p;
                xr[p] = *(const float4*)&X[(size_t)(tileM + (id >> 3)) * DM + k0 + 32 + (id & 7) * 4];
                wr[p] = *(const float4*)&W[(size_t)(k0 + 32 + (id >> 5)) * DM + tileN + (id & 31) * 4];
            }
        }

#pragma unroll
        for (int ks = 0; ks < 4; ks++) {
            uint32_t ahi[4][4], alo[4][4];
#pragma unroll
            for (int mt = 0; mt < 4; mt++) {
                uint32_t addr = As_base +
                    4u * (uint32_t)((wm * 64 + mt * 16) * ASTR + ks * 8 + a_lane_off);
                uint32_t r0, r1, r2, r3;
                asm volatile("ldmatrix.sync.aligned.m8n8.x4.shared.b16 {%0,%1,%2,%3}, [%4];"
                             : "=r"(r0), "=r"(r1), "=r"(r2), "=r"(r3) : "r"(addr));
                uint32_t rs[4] = {r0, r1, r2, r3};
#pragma unroll
                for (int i = 0; i < 4; i++) {
                    float a = __uint_as_float(rs[i]);
                    uint32_t h = f2tf32(a);
                    ahi[mt][i] = h;
                    alo[mt][i] = f2tf32(a - __uint_as_float(h));
                }
            }
            uint32_t bhi[4][2], blo[4][2];
#pragma unroll
            for (int nt = 0; nt < 4; nt++) {
                int col = wn * 32 + nt * 8 + (lane >> 2);
                int krow = ks * 8 + (lane & 3);
                float b0 = Ws[krow * WSTR + col];
                float b1 = Ws[(krow + 4) * WSTR + col];
                uint32_t h0 = f2tf32(b0), h1 = f2tf32(b1);
                bhi[nt][0] = h0; bhi[nt][1] = h1;
                blo[nt][0] = f2tf32(b0 - __uint_as_float(h0));
                blo[nt][1] = f2tf32(b1 - __uint_as_float(h1));
            }
#pragma unroll
            for (int mt = 0; mt < 4; mt++)
#pragma unroll
                for (int nt = 0; nt < 4; nt++) {
                    mma_tf32(acc[mt][nt], ahi[mt], bhi[nt]);
                    mma_tf32(acc[mt][nt], ahi[mt], blo[nt]);
                    mma_tf32(acc[mt][nt], alo[mt], bhi[nt]);
                }
        }
    }

    // Epilogue: bias + remap to [b,h,s,d]
#pragma unroll
    for (int mt = 0; mt < 4; mt++) {
        int r0 = tileM + wm * 64 + mt * 16 + (lane >> 2);
#pragma unroll
        for (int nt = 0; nt < 4; nt++) {
            int c0 = tileN + wn * 32 + nt * 8 + (lane & 3) * 2;
            int h = c0 >> 6, d = c0 & 63;
            float bv0 = bias[c0], bv1 = bias[c0 + 1];
#pragma unroll
            for (int half = 0; half < 2; half++) {
                int r = r0 + half * 8;
                int bb = r >> 10, s = r & (SS - 1);
                float2 o = make_float2(acc[mt][nt][half * 2 + 0] + bv0,
                                       acc[mt][nt][half * 2 + 1] + bv1);
                *(float2*)&out[(((size_t)(bb * NH + h) * SS + s) << 6) + d] = o;
            }
        }
    }
}

// ---------------------------------------------------------------------------
// Fused attention, LDS-optimized SIMT.
// Per CTA: (b, h, 32 q-rows). Thread row-group qg=tid&7 owns rows {qg+8i}
// (stride 8*68 words -> conflict-free float4 LDS). Full score row in smem,
// one-pass softmax fused with attn write, PV from smem.
// ---------------------------------------------------------------------------
#define SQS 68
#define SKS 68
#define SSS 1028
#define ATTN_SMEM_FLOATS (32 * SQS + 128 * SKS + 32 * SSS)
#define ATTN_SMEM_BYTES (ATTN_SMEM_FLOATS * 4)

__global__ __launch_bounds__(256) void attn_kernel(
    float* __restrict__ ctx_out, float* __restrict__ attn_out)
{
    extern __shared__ float sm[];
    float* sQ  = sm;                 // 32 x 68
    float* sKV = sQ + 32 * SQS;      // 128 x 68 (K tile, later V tile)
    float* sS  = sKV + 128 * SKS;    // 32 x 1028

    const int tid = threadIdx.x;
    const int qt = blockIdx.x;       // 0..31
    const int h  = blockIdx.y;       // 0..15
    const int b  = blockIdx.z;       // 0..3

    const float* Qb = g_Q + ((size_t)(b * NH + h) * SS + qt * 32) * DK;
    const float* Kb = g_K + (size_t)(b * NH + h) * SS * DK;
    const float* Vb = g_V + (size_t)(b * NH + h) * SS * DV;

    // Load Q tile (32 x 64): 512 float4, 2 per thread
#pragma unroll
    for (int p = 0; p < 2; p++) {
        int id = tid + 256 * p;
        int row = id >> 4, c4 = (id & 15) * 4;
        *(float4*)&sQ[row * SQS + c4] = *(const float4*)&Qb[row * DK + c4];
    }

    const int qg = tid & 7;    // q row group: rows qg+8i
    const int cg = tid >> 3;   // 0..31: score cols cg*4..cg*4+3

    // ---- Scores: S = (Q K^T)/8 ----
    for (int kt = 0; kt < 8; kt++) {
        __syncthreads();
#pragma unroll
        for (int p = 0; p < 8; p++) {
            int id = tid + 256 * p;
            int row = id >> 4, c4 = (id & 15) * 4;
            *(float4*)&sKV[row * SKS + c4] = *(const float4*)&Kb[(kt * 128 + row) * DK + c4];
        }
        __syncthreads();

        float acc[4][4];
#pragma unroll
        for (int i = 0; i < 4; i++)
#pragma unroll
            for (int j = 0; j < 4; j++) acc[i][j] = 0.0f;

#pragma unroll 4
        for (int d4 = 0; d4 < 16; d4++) {
            float4 a4[4], b4[4];
#pragma unroll
            for (int i = 0; i < 4; i++)
                a4[i] = *(const float4*)&sQ[(qg + 8 * i) * SQS + d4 * 4];
#pragma unroll
            for (int j = 0; j < 4; j++)
                b4[j] = *(const float4*)&sKV[(cg * 4 + j) * SKS + d4 * 4];
#pragma unroll
            for (int i = 0; i < 4; i++)
#pragma unroll
                for (int j = 0; j < 4; j++)
                    acc[i][j] += a4[i].x * b4[j].x + a4[i].y * b4[j].y
                               + a4[i].z * b4[j].z + a4[i].w * b4[j].w;
        }
#pragma unroll
        for (int i = 0; i < 4; i++) {
            float4 o = make_float4(acc[i][0] * 0.125f, acc[i][1] * 0.125f,
                                   acc[i][2] * 0.125f, acc[i][3] * 0.125f);
            *(float4*)&sS[(qg + 8 * i) * SSS + kt * 128 + cg * 4] = o;
        }
    }
    __syncthreads();

    // ---- Softmax per row (warp owns 4 rows), fused attn write ----
    const int warp = tid >> 5;
    const int lane = tid & 31;
#pragma unroll
    for (int rr = 0; rr < 4; rr++) {
        int r = warp * 4 + rr;
        float* row = sS + r * SSS;
        float mx = -3.0e38f;
#pragma unroll
        for (int k = 0; k < 8; k++) {
            float4 v = *(const float4*)&row[lane * 4 + 128 * k];
            mx = fmaxf(mx, fmaxf(fmaxf(v.x, v.y), fmaxf(v.z, v.w)));
        }
#pragma unroll
        for (int o = 16; o > 0; o >>= 1) mx = fmaxf(mx, __shfl_xor_sync(0xffffffffu, mx, o));
        float sum = 0.0f;
        float4 e[8];
#pragma unroll
        for (int k = 0; k < 8; k++) {
            float4 v = *(const float4*)&row[lane * 4 + 128 * k];
            e[k].x = __expf(v.x - mx); e[k].y = __expf(v.y - mx);
            e[k].z = __expf(v.z - mx); e[k].w = __expf(v.w - mx);
            sum += e[k].x + e[k].y + e[k].z + e[k].w;
        }
#pragma unroll
        for (int o = 16; o > 0; o >>= 1) sum += __shfl_xor_sync(0xffffffffu, sum, o);
        float inv = 1.0f / sum;
        float* arow = attn_out + ((size_t)(b * NH + h) * SS + qt * 32 + r) * SS;
#pragma unroll
        for (int k = 0; k < 8; k++) {
            float4 p = make_float4(e[k].x * inv, e[k].y * inv, e[k].z * inv, e[k].w * inv);
            *(float4*)&row[lane * 4 + 128 * k] = p;
            *(float4*)&arow[lane * 4 + 128 * k] = p;
        }
    }

    // ---- PV: context = P @ V ----
    const int dg = tid >> 3;   // 0..31 -> d cols {2dg, 2dg+1}
    float acc2[4][2];
#pragma unroll
    for (int i = 0; i < 4; i++) { acc2[i][0] = 0.0f; acc2[i][1] = 0.0f; }

    for (int vt = 0; vt < 8; vt++) {
        __syncthreads();
#pragma unroll
        for (int p = 0; p < 8; p++) {
            int id = tid + 256 * p;
            int row = id >> 4, c4 = (id & 15) * 4;
            *(float4*)&sKV[row * SKS + c4] = *(const float4*)&Vb[(vt * 128 + row) * DV + c4];
        }
        __syncthreads();
#pragma unroll 4
        for (int k4 = 0; k4 < 32; k4++) {
            float4 p4[4];
#pragma unroll
            for (int i = 0; i < 4; i++)
                p4[i] = *(const float4*)&sS[(qg + 8 * i) * SSS + vt * 128 + k4 * 4];
            float2 v2[4];
#pragma unroll
            for (int dd = 0; dd < 4; dd++)
                v2[dd] = *(const float2*)&sKV[(k4 * 4 + dd) * SKS + dg * 2];
#pragma unroll
            for (int i = 0; i < 4; i++) {
                acc2[i][0] += p4[i].x * v2[0].x + p4[i].y * v2[1].x
                            + p4[i].z * v2[2].x + p4[i].w * v2[3].x;
                acc2[i][1] += p4[i].x * v2[0].y + p4[i].y * v2[1].y
                            + p4[i].z * v2[2].y + p4[i].w * v2[3].y;
            }
        }
    }

    // Write context in [b, s, h*64 + d]
#pragma unroll
    for (int i = 0; i < 4; i++) {
        int q = qt * 32 + qg + 8 * i;
        *(float2*)&ctx_out[((size_t)b * SS + q) * (NH * DV) + h * DV + dg * 2] =
            make_float2(acc2[i][0], acc2[i][1]);
    }
}

// ---------------------------------------------------------------------------
// Launch
// ---------------------------------------------------------------------------
extern "C" void kernel_launch(void* const* d_in, const int* in_sizes, int n_in,
                              void* d_out, int out_size)
{
    const float* q  = (const float*)d_in[0];
    const float* k  = (const float*)d_in[1];
    const float* v  = (const float*)d_in[2];
    const float* wq = (const float*)d_in[3];
    const float* wk = (const float*)d_in[4];
    const float* wv = (const float*)d_in[5];
    const float* bq = (const float*)d_in[6];
    const float* bk = (const float*)d_in[7];
    const float* bv = (const float*)d_in[8];
    // d_in[9] = attn_mask (falsy) -> no masking

    float* ctx  = (float*)d_out;
    float* attn = (float*)d_out + (size_t)BB * SS * NH * DV;

    (void)cudaFuncSetAttribute(attn_kernel,
                               cudaFuncAttributeMaxDynamicSharedMemorySize,
                               ATTN_SMEM_BYTES);

    dim3 pgrid(DM / 128, (BB * SS) / 128, 3);
    proj_mma_kernel<<<pgrid, 256>>>(q, k, v, wq, wk, wv, bq, bk, bv);

    dim3 agrid(SS / 32, NH, BB);
    attn_kernel<<<agrid, 256, ATTN_SMEM_BYTES>>>(ctx, attn);
}

// round 4
// speedup vs baseline: 3.0173x; 3.0173x over previous
#include <cuda_runtime.h>
#include <cuda_bf16.h>
#include <cstdint>
#include <math.h>

// Problem dims
#define BB 4
#define SS 1024
#define DM 1024
#define NH 16
#define DK 64
#define DV 64

// Scratch for projected Q/K/V in [b, h, s, d] layout
__device__ float g_Q[BB * NH * SS * DK];
__device__ float g_K[BB * NH * SS * DK];
__device__ float g_V[BB * NH * SS * DV];

// ---------------------------------------------------------------------------
// tf32 mma helpers
// ---------------------------------------------------------------------------
__device__ __forceinline__ uint32_t f2tf32(float x) {
    uint32_t r;
    asm("cvt.rna.tf32.f32 %0, %1;" : "=r"(r) : "f"(x));
    return r;
}

__device__ __forceinline__ void mma_tf32(float c[4], const uint32_t a[4], const uint32_t b[2]) {
    asm volatile(
        "mma.sync.aligned.m16n8k8.row.col.f32.tf32.tf32.f32 "
        "{%0,%1,%2,%3}, {%4,%5,%6,%7}, {%8,%9}, {%0,%1,%2,%3};"
        : "+f"(c[0]), "+f"(c[1]), "+f"(c[2]), "+f"(c[3])
        : "r"(a[0]), "r"(a[1]), "r"(a[2]), "r"(a[3]), "r"(b[0]), "r"(b[1]));
}

// ldmatrix x4 of an m16k8 fp32 fragment (viewed as 8x8 b16 blocks).
__device__ __forceinline__ void ldsm_x4(uint32_t r[4], uint32_t addr) {
    asm volatile("ldmatrix.sync.aligned.m8n8.x4.shared.b16 {%0,%1,%2,%3}, [%4];"
                 : "=r"(r[0]), "=r"(r[1]), "=r"(r[2]), "=r"(r[3]) : "r"(addr));
}

// ---------------------------------------------------------------------------
// Projection GEMM via single-pass tf32 mma.sync.
// Y[4096,1024] = X[4096,1024] @ W[1024,1024] + bias, remapped to [b,h,s,d].
// Tiles: 128x128x32. 8 warps = 2(M) x 4(N); warp tile 64x32 via 4x4 m16n8.
// ---------------------------------------------------------------------------
#define ASTR 36   // As row stride (floats)
#define WSTR 136  // Ws row stride (floats)

__global__ __launch_bounds__(256, 2) void proj_mma_kernel(
    const float* __restrict__ xq, const float* __restrict__ xk, const float* __restrict__ xv,
    const float* __restrict__ wq, const float* __restrict__ wk, const float* __restrict__ wv,
    const float* __restrict__ bq, const float* __restrict__ bk, const float* __restrict__ bv)
{
    __shared__ float As[128 * ASTR];
    __shared__ float Ws[32 * WSTR];

    const float* X; const float* W; const float* bias; float* out;
    int which = blockIdx.z;
    if (which == 0)      { X = xq; W = wq; bias = bq; out = g_Q; }
    else if (which == 1) { X = xk; W = wk; bias = bk; out = g_K; }
    else                 { X = xv; W = wv; bias = bv; out = g_V; }

    const int tid  = threadIdx.x;
    const int warp = tid >> 5;
    const int lane = tid & 31;
    const int wm   = warp >> 2;   // 0..1
    const int wn   = warp & 3;    // 0..3
    const int tileM = blockIdx.y * 128;
    const int tileN = blockIdx.x * 128;

    const int lrow = (lane & 7) + ((lane >> 3) & 1) * 8;
    const int lkc  = (lane >> 4) * 4;
    const int a_lane_off = lrow * ASTR + lkc;

    const uint32_t As_base = (uint32_t)__cvta_generic_to_shared(As);

    float acc[4][4][4];
#pragma unroll
    for (int mt = 0; mt < 4; mt++)
#pragma unroll
        for (int nt = 0; nt < 4; nt++)
#pragma unroll
            for (int i = 0; i < 4; i++) acc[mt][nt][i] = 0.0f;

    float4 xr[4], wr[4];
#pragma unroll
    for (int p = 0; p < 4; p++) {
        int id = tid + 256 * p;
        xr[p] = *(const float4*)&X[(size_t)(tileM + (id >> 3)) * DM + (id & 7) * 4];
        wr[p] = *(const float4*)&W[(size_t)(id >> 5) * DM + tileN + (id & 31) * 4];
    }

    for (int k0 = 0; k0 < DM; k0 += 32) {
        __syncthreads();
#pragma unroll
        for (int p = 0; p < 4; p++) {
            int id = tid + 256 * p;
            *(float4*)&As[(id >> 3) * ASTR + (id & 7) * 4] = xr[p];
            *(float4*)&Ws[(id >> 5) * WSTR + (id & 31) * 4] = wr[p];
        }
        __syncthreads();

        if (k0 + 32 < DM) {
#pragma unroll
            for (int p = 0; p < 4; p++) {
                int id = tid + 256 * p;
                xr[p] = *(const float4*)&X[(size_t)(tileM + (id >> 3)) * DM + k0 + 32 + (id & 7) * 4];
                wr[p] = *(const float4*)&W[(size_t)(k0 + 32 + (id >> 5)) * DM + tileN + (id & 31) * 4];
            }
        }

#pragma unroll
        for (int ks = 0; ks < 4; ks++) {
            uint32_t a[4][4];
#pragma unroll
            for (int mt = 0; mt < 4; mt++) {
                uint32_t addr = As_base +
                    4u * (uint32_t)((wm * 64 + mt * 16) * ASTR + ks * 8 + a_lane_off);
                uint32_t r[4];
                ldsm_x4(r, addr);
#pragma unroll
                for (int i = 0; i < 4; i++) a[mt][i] = f2tf32(__uint_as_float(r[i]));
            }
            uint32_t bfr[4][2];
#pragma unroll
            for (int nt = 0; nt < 4; nt++) {
                int col = wn * 32 + nt * 8 + (lane >> 2);
                int krow = ks * 8 + (lane & 3);
                bfr[nt][0] = f2tf32(Ws[krow * WSTR + col]);
                bfr[nt][1] = f2tf32(Ws[(krow + 4) * WSTR + col]);
            }
#pragma unroll
            for (int mt = 0; mt < 4; mt++)
#pragma unroll
                for (int nt = 0; nt < 4; nt++)
                    mma_tf32(acc[mt][nt], a[mt], bfr[nt]);
        }
    }

    // Epilogue: bias + remap to [b,h,s,d]
#pragma unroll
    for (int mt = 0; mt < 4; mt++) {
        int r0 = tileM + wm * 64 + mt * 16 + (lane >> 2);
#pragma unroll
        for (int nt = 0; nt < 4; nt++) {
            int c0 = tileN + wn * 32 + nt * 8 + (lane & 3) * 2;
            int h = c0 >> 6, d = c0 & 63;
            float bv0 = bias[c0], bv1 = bias[c0 + 1];
#pragma unroll
            for (int half = 0; half < 2; half++) {
                int r = r0 + half * 8;
                int bb = r >> 10, s = r & (SS - 1);
                float2 o = make_float2(acc[mt][nt][half * 2 + 0] + bv0,
                                       acc[mt][nt][half * 2 + 1] + bv1);
                *(float2*)&out[(((size_t)(bb * NH + h) * SS + s) << 6) + d] = o;
            }
        }
    }
}

// ---------------------------------------------------------------------------
// Fused attention with tf32 mma for scores and PV.
// Per CTA: (b, h, 32 q-rows), 256 threads / 8 warps.
// Scores: warp w owns cols [w*16, w*16+16) of each 128-wide K tile.
// PV: warp w owns d-cols [w*8, w*8+8).
// Full 32x1024 score row in smem; one-pass softmax fused with attn write.
// ---------------------------------------------------------------------------
#define SQS 68
#define SKS 68
#define SSS 1028
#define ATTN_SMEM_FLOATS (32 * SQS + 128 * SKS + 32 * SSS)
#define ATTN_SMEM_BYTES (ATTN_SMEM_FLOATS * 4)

__global__ __launch_bounds__(256) void attn_kernel(
    float* __restrict__ ctx_out, float* __restrict__ attn_out)
{
    extern __shared__ float sm[];
    float* sQ  = sm;                 // 32 x 68
    float* sKV = sQ + 32 * SQS;      // 128 x 68 (K tile, later V tile)
    float* sS  = sKV + 128 * SKS;    // 32 x 1028

    const int tid  = threadIdx.x;
    const int warp = tid >> 5;
    const int lane = tid & 31;
    const int qt = blockIdx.x;       // 0..31
    const int h  = blockIdx.y;       // 0..15
    const int b  = blockIdx.z;       // 0..3

    const float* Qb = g_Q + ((size_t)(b * NH + h) * SS + qt * 32) * DK;
    const float* Kb = g_K + (size_t)(b * NH + h) * SS * DK;
    const float* Vb = g_V + (size_t)(b * NH + h) * SS * DV;

    const int lrow = (lane & 7) + ((lane >> 3) & 1) * 8;
    const int lkc  = (lane >> 4) * 4;
    const uint32_t sQ_base = (uint32_t)__cvta_generic_to_shared(sQ);
    const uint32_t sS_base = (uint32_t)__cvta_generic_to_shared(sS);

    // Load Q tile (32 x 64)
#pragma unroll
    for (int p = 0; p < 2; p++) {
        int id = tid + 256 * p;
        int row = id >> 4, c4 = (id & 15) * 4;
        *(float4*)&sQ[row * SQS + c4] = *(const float4*)&Qb[row * DK + c4];
    }
    __syncthreads();

    // Preload Q fragments (tf32) for all 8 k-steps, both m16 tiles
    uint32_t aq[2][8][4];
#pragma unroll
    for (int mt = 0; mt < 2; mt++)
#pragma unroll
        for (int ks = 0; ks < 8; ks++) {
            uint32_t addr = sQ_base +
                4u * (uint32_t)((mt * 16 + lrow) * SQS + ks * 8 + lkc);
            uint32_t r[4];
            ldsm_x4(r, addr);
#pragma unroll
            for (int i = 0; i < 4; i++) aq[mt][ks][i] = f2tf32(__uint_as_float(r[i]));
        }

    // ---- Scores: S = (Q K^T)/8 ----
    for (int kt = 0; kt < 8; kt++) {
        __syncthreads();
#pragma unroll
        for (int p = 0; p < 8; p++) {
            int id = tid + 256 * p;
            int row = id >> 4, c4 = (id & 15) * 4;
            *(float4*)&sKV[row * SKS + c4] = *(const float4*)&Kb[(kt * 128 + row) * DK + c4];
        }
        __syncthreads();

        float c[2][2][4];
#pragma unroll
        for (int mt = 0; mt < 2; mt++)
#pragma unroll
            for (int nt = 0; nt < 2; nt++)
#pragma unroll
                for (int i = 0; i < 4; i++) c[mt][nt][i] = 0.0f;

#pragma unroll
        for (int ks = 0; ks < 8; ks++) {
            uint32_t bfr[2][2];
#pragma unroll
            for (int nt = 0; nt < 2; nt++) {
                int ncol = warp * 16 + nt * 8 + (lane >> 2);
                int krow = ks * 8 + (lane & 3);
                bfr[nt][0] = f2tf32(sKV[ncol * SKS + krow]);
                bfr[nt][1] = f2tf32(sKV[ncol * SKS + krow + 4]);
            }
#pragma unroll
            for (int mt = 0; mt < 2; mt++)
#pragma unroll
                for (int nt = 0; nt < 2; nt++)
                    mma_tf32(c[mt][nt], aq[mt][ks], bfr[nt]);
        }
#pragma unroll
        for (int mt = 0; mt < 2; mt++) {
            int r = mt * 16 + (lane >> 2);
#pragma unroll
            for (int nt = 0; nt < 2; nt++) {
                int col = kt * 128 + warp * 16 + nt * 8 + 2 * (lane & 3);
                *(float2*)&sS[r * SSS + col] =
                    make_float2(c[mt][nt][0] * 0.125f, c[mt][nt][1] * 0.125f);
                *(float2*)&sS[(r + 8) * SSS + col] =
                    make_float2(c[mt][nt][2] * 0.125f, c[mt][nt][3] * 0.125f);
            }
        }
    }
    __syncthreads();

    // ---- Softmax per row (warp owns 4 rows), fused attn write ----
#pragma unroll
    for (int rr = 0; rr < 4; rr++) {
        int r = warp * 4 + rr;
        float* row = sS + r * SSS;
        float mx = -3.0e38f;
#pragma unroll
        for (int k = 0; k < 8; k++) {
            float4 v = *(const float4*)&row[lane * 4 + 128 * k];
            mx = fmaxf(mx, fmaxf(fmaxf(v.x, v.y), fmaxf(v.z, v.w)));
        }
#pragma unroll
        for (int o = 16; o > 0; o >>= 1) mx = fmaxf(mx, __shfl_xor_sync(0xffffffffu, mx, o));
        float sum = 0.0f;
        float4 e[8];
#pragma unroll
        for (int k = 0; k < 8; k++) {
            float4 v = *(const float4*)&row[lane * 4 + 128 * k];
            e[k].x = __expf(v.x - mx); e[k].y = __expf(v.y - mx);
            e[k].z = __expf(v.z - mx); e[k].w = __expf(v.w - mx);
            sum += e[k].x + e[k].y + e[k].z + e[k].w;
        }
#pragma unroll
        for (int o = 16; o > 0; o >>= 1) sum += __shfl_xor_sync(0xffffffffu, sum, o);
        float inv = 1.0f / sum;
        float* arow = attn_out + ((size_t)(b * NH + h) * SS + qt * 32 + r) * SS;
#pragma unroll
        for (int k = 0; k < 8; k++) {
            float4 p = make_float4(e[k].x * inv, e[k].y * inv, e[k].z * inv, e[k].w * inv);
            *(float4*)&row[lane * 4 + 128 * k] = p;
            *(float4*)&arow[lane * 4 + 128 * k] = p;
        }
    }

    // ---- PV: context = P @ V ----
    float acc2[2][4];
#pragma unroll
    for (int mt = 0; mt < 2; mt++)
#pragma unroll
        for (int i = 0; i < 4; i++) acc2[mt][i] = 0.0f;

    for (int vt = 0; vt < 8; vt++) {
        __syncthreads();
#pragma unroll
        for (int p = 0; p < 8; p++) {
            int id = tid + 256 * p;
            int row = id >> 4, c4 = (id & 15) * 4;
            *(float4*)&sKV[row * SKS + c4] = *(const float4*)&Vb[(vt * 128 + row) * DV + c4];
        }
        __syncthreads();

#pragma unroll
        for (int ks = 0; ks < 16; ks++) {
            uint32_t ap[2][4];
#pragma unroll
            for (int mt = 0; mt < 2; mt++) {
                uint32_t addr = sS_base +
                    4u * (uint32_t)((mt * 16 + lrow) * SSS + vt * 128 + ks * 8 + lkc);
                uint32_t r[4];
                ldsm_x4(r, addr);
#pragma unroll
                for (int i = 0; i < 4; i++) ap[mt][i] = f2tf32(__uint_as_float(r[i]));
            }
            uint32_t bfr[2];
            {
                int ncol = warp * 8 + (lane >> 2);
                int krow = ks * 8 + (lane & 3);
                bfr[0] = f2tf32(sKV[krow * SKS + ncol]);
                bfr[1] = f2tf32(sKV[(krow + 4) * SKS + ncol]);
            }
            mma_tf32(acc2[0], ap[0], bfr);
            mma_tf32(acc2[1], ap[1], bfr);
        }
    }

    // Write context in [b, s, h*64 + d]
#pragma unroll
    for (int mt = 0; mt < 2; mt++) {
        int r = qt * 32 + mt * 16 + (lane >> 2);
        int col = h * DV + warp * 8 + 2 * (lane & 3);
        *(float2*)&ctx_out[((size_t)b * SS + r) * (NH * DV) + col] =
            make_float2(acc2[mt][0], acc2[mt][1]);
        *(float2*)&ctx_out[((size_t)b * SS + r + 8) * (NH * DV) + col] =
            make_float2(acc2[mt][2], acc2[mt][3]);
    }
}

// ---------------------------------------------------------------------------
// Launch
// ---------------------------------------------------------------------------
extern "C" void kernel_launch(void* const* d_in, const int* in_sizes, int n_in,
                              void* d_out, int out_size)
{
    const float* q  = (const float*)d_in[0];
    const float* k  = (const float*)d_in[1];
    const float* v  = (const float*)d_in[2];
    const float* wq = (const float*)d_in[3];
    const float* wk = (const float*)d_in[4];
    const float* wv = (const float*)d_in[5];
    const float* bq = (const float*)d_in[6];
    const float* bk = (const float*)d_in[7];
    const float* bv = (const float*)d_in[8];
    // d_in[9] = attn_mask (falsy) -> no masking

    float* ctx  = (float*)d_out;
    float* attn = (float*)d_out + (size_t)BB * SS * NH * DV;

    (void)cudaFuncSetAttribute(attn_kernel,
                               cudaFuncAttributeMaxDynamicSharedMemorySize,
                               ATTN_SMEM_BYTES);

    dim3 pgrid(DM / 128, (BB * SS) / 128, 3);
    proj_mma_kernel<<<pgrid, 256>>>(q, k, v, wq, wk, wv, bq, bk, bv);

    dim3 agrid(SS / 32, NH, BB);
    attn_kernel<<<agrid, 256, ATTN_SMEM_BYTES>>>(ctx, attn);
}

// round 5
// speedup vs baseline: 3.5911x; 1.1902x over previous
#include <cuda_runtime.h>
#include <cuda_bf16.h>
#include <cstdint>
#include <math.h>

// Problem dims
#define BB 4
#define SS 1024
#define DM 1024
#define NH 16
#define DK 64
#define DV 64

// Scratch for projected Q/K/V in [b, h, s, d] layout (stored tf32-rounded)
__device__ float g_Q[BB * NH * SS * DK];
__device__ float g_K[BB * NH * SS * DK];
__device__ float g_V[BB * NH * SS * DV];

// ---------------------------------------------------------------------------
// helpers
// ---------------------------------------------------------------------------
__device__ __forceinline__ uint32_t f2tf32(float x) {
    uint32_t r;
    asm("cvt.rna.tf32.f32 %0, %1;" : "=r"(r) : "f"(x));
    return r;
}
__device__ __forceinline__ float rnd_tf32(float x) {
    return __uint_as_float(f2tf32(x));
}

__device__ __forceinline__ void mma_tf32(float c[4], const uint32_t a[4], const uint32_t b[2]) {
    asm volatile(
        "mma.sync.aligned.m16n8k8.row.col.f32.tf32.tf32.f32 "
        "{%0,%1,%2,%3}, {%4,%5,%6,%7}, {%8,%9}, {%0,%1,%2,%3};"
        : "+f"(c[0]), "+f"(c[1]), "+f"(c[2]), "+f"(c[3])
        : "r"(a[0]), "r"(a[1]), "r"(a[2]), "r"(a[3]), "r"(b[0]), "r"(b[1]));
}

__device__ __forceinline__ void ldsm_x4(uint32_t r[4], uint32_t addr) {
    asm volatile("ldmatrix.sync.aligned.m8n8.x4.shared.b16 {%0,%1,%2,%3}, [%4];"
                 : "=r"(r[0]), "=r"(r[1]), "=r"(r[2]), "=r"(r[3]) : "r"(addr));
}

__device__ __forceinline__ void cp16(uint32_t smem, const void* g) {
    asm volatile("cp.async.cg.shared.global [%0], [%1], 16;" :: "r"(smem), "l"(g));
}
#define CP_COMMIT() asm volatile("cp.async.commit_group;")
#define CP_WAIT0()  asm volatile("cp.async.wait_group 0;")

// ---------------------------------------------------------------------------
// Projection GEMM, tf32 mma.sync. Operands rounded ONCE at smem store;
// outputs rounded at epilogue (consumed raw by attn).
// ---------------------------------------------------------------------------
#define ASTR 36
#define WSTR 136

__global__ __launch_bounds__(256, 2) void proj_mma_kernel(
    const float* __restrict__ xq, const float* __restrict__ xk, const float* __restrict__ xv,
    const float* __restrict__ wq, const float* __restrict__ wk, const float* __restrict__ wv,
    const float* __restrict__ bq, const float* __restrict__ bk, const float* __restrict__ bv)
{
    __shared__ float As[128 * ASTR];
    __shared__ float Ws[32 * WSTR];

    const float* X; const float* W; const float* bias; float* out;
    int which = blockIdx.z;
    if (which == 0)      { X = xq; W = wq; bias = bq; out = g_Q; }
    else if (which == 1) { X = xk; W = wk; bias = bk; out = g_K; }
    else                 { X = xv; W = wv; bias = bv; out = g_V; }

    const int tid  = threadIdx.x;
    const int warp = tid >> 5;
    const int lane = tid & 31;
    const int wm   = warp >> 2;
    const int wn   = warp & 3;
    const int tileM = blockIdx.y * 128;
    const int tileN = blockIdx.x * 128;

    const int lrow = (lane & 7) + ((lane >> 3) & 1) * 8;
    const int lkc  = (lane >> 4) * 4;
    const int a_lane_off = lrow * ASTR + lkc;

    const uint32_t As_base = (uint32_t)__cvta_generic_to_shared(As);

    float acc[4][4][4];
#pragma unroll
    for (int mt = 0; mt < 4; mt++)
#pragma unroll
        for (int nt = 0; nt < 4; nt++)
#pragma unroll
            for (int i = 0; i < 4; i++) acc[mt][nt][i] = 0.0f;

    float4 xr[4], wr[4];
#pragma unroll
    for (int p = 0; p < 4; p++) {
        int id = tid + 256 * p;
        xr[p] = *(const float4*)&X[(size_t)(tileM + (id >> 3)) * DM + (id & 7) * 4];
        wr[p] = *(const float4*)&W[(size_t)(id >> 5) * DM + tileN + (id & 31) * 4];
    }

    for (int k0 = 0; k0 < DM; k0 += 32) {
        __syncthreads();
#pragma unroll
        for (int p = 0; p < 4; p++) {
            int id = tid + 256 * p;
            float4 xv4 = make_float4(rnd_tf32(xr[p].x), rnd_tf32(xr[p].y),
                                     rnd_tf32(xr[p].z), rnd_tf32(xr[p].w));
            float4 wv4 = make_float4(rnd_tf32(wr[p].x), rnd_tf32(wr[p].y),
                                     rnd_tf32(wr[p].z), rnd_tf32(wr[p].w));
            *(float4*)&As[(id >> 3) * ASTR + (id & 7) * 4] = xv4;
            *(float4*)&Ws[(id >> 5) * WSTR + (id & 31) * 4] = wv4;
        }
        __syncthreads();

        if (k0 + 32 < DM) {
#pragma unroll
            for (int p = 0; p < 4; p++) {
                int id = tid + 256 * p;
                xr[p] = *(const float4*)&X[(size_t)(tileM + (id >> 3)) * DM + k0 + 32 + (id & 7) * 4];
                wr[p] = *(const float4*)&W[(size_t)(k0 + 32 + (id >> 5)) * DM + tileN + (id & 31) * 4];
            }
        }

#pragma unroll
        for (int ks = 0; ks < 4; ks++) {
            uint32_t a[4][4];
#pragma unroll
            for (int mt = 0; mt < 4; mt++) {
                uint32_t addr = As_base +
                    4u * (uint32_t)((wm * 64 + mt * 16) * ASTR + ks * 8 + a_lane_off);
                ldsm_x4(a[mt], addr);
            }
            uint32_t bfr[4][2];
#pragma unroll
            for (int nt = 0; nt < 4; nt++) {
                int col = wn * 32 + nt * 8 + (lane >> 2);
                int krow = ks * 8 + (lane & 3);
                bfr[nt][0] = __float_as_uint(Ws[krow * WSTR + col]);
                bfr[nt][1] = __float_as_uint(Ws[(krow + 4) * WSTR + col]);
            }
#pragma unroll
            for (int mt = 0; mt < 4; mt++)
#pragma unroll
                for (int nt = 0; nt < 4; nt++)
                    mma_tf32(acc[mt][nt], a[mt], bfr[nt]);
        }
    }

    // Epilogue: bias + tf32-round + remap to [b,h,s,d]
#pragma unroll
    for (int mt = 0; mt < 4; mt++) {
        int r0 = tileM + wm * 64 + mt * 16 + (lane >> 2);
#pragma unroll
        for (int nt = 0; nt < 4; nt++) {
            int c0 = tileN + wn * 32 + nt * 8 + (lane & 3) * 2;
            int h = c0 >> 6, d = c0 & 63;
            float bv0 = bias[c0], bv1 = bias[c0 + 1];
#pragma unroll
            for (int half = 0; half < 2; half++) {
                int r = r0 + half * 8;
                int bb = r >> 10, s = r & (SS - 1);
                float2 o = make_float2(rnd_tf32(acc[mt][nt][half * 2 + 0] + bv0),
                                       rnd_tf32(acc[mt][nt][half * 2 + 1] + bv1));
                *(float2*)&out[(((size_t)(bb * NH + h) * SS + s) << 6) + d] = o;
            }
        }
    }
}

// ---------------------------------------------------------------------------
// Fused attention, tf32 mma, cp.async double-buffered K/V tiles.
// Per CTA: (b, h, 32 q-rows), 256 threads / 8 warps.
// ---------------------------------------------------------------------------
#define SQS 68
#define SKS 68
#define SSS 1028
#define ATTN_SMEM_FLOATS (32 * SQS + 2 * 128 * SKS + 32 * SSS)
#define ATTN_SMEM_BYTES (ATTN_SMEM_FLOATS * 4)

__global__ __launch_bounds__(256) void attn_kernel(
    float* __restrict__ ctx_out, float* __restrict__ attn_out)
{
    extern __shared__ float sm[];
    float* sQ  = sm;                        // 32 x 68
    float* sB0 = sQ + 32 * SQS;             // 128 x 68 (buf 0)
    float* sB1 = sB0 + 128 * SKS;           // 128 x 68 (buf 1)
    float* sS  = sB1 + 128 * SKS;           // 32 x 1028

    const int tid  = threadIdx.x;
    const int warp = tid >> 5;
    const int lane = tid & 31;
    const int qt = blockIdx.x;
    const int h  = blockIdx.y;
    const int b  = blockIdx.z;

    const float* Qb = g_Q + ((size_t)(b * NH + h) * SS + qt * 32) * DK;
    const float* Kb = g_K + (size_t)(b * NH + h) * SS * DK;
    const float* Vb = g_V + (size_t)(b * NH + h) * SS * DV;

    const int lrow = (lane & 7) + ((lane >> 3) & 1) * 8;
    const int lkc  = (lane >> 4) * 4;
    const uint32_t sQ_base = (uint32_t)__cvta_generic_to_shared(sQ);
    const uint32_t sS_base = (uint32_t)__cvta_generic_to_shared(sS);
    const uint32_t buf_base[2] = {
        (uint32_t)__cvta_generic_to_shared(sB0),
        (uint32_t)__cvta_generic_to_shared(sB1)
    };
    float* const buf_ptr[2] = { sB0, sB1 };

    // per-thread tile-copy coordinates (128x64 tile, 8 float4 per thread)
    const int crow = tid >> 4;          // 0..15 (+16 per p)
    const int cc4  = (tid & 15) * 4;

    // ---- issue Q + K0 (group 0) ----
#pragma unroll
    for (int p = 0; p < 2; p++) {
        int row = (tid + 256 * p) >> 4;
        cp16(sQ_base + 4u * (uint32_t)(row * SQS + cc4), &Qb[row * DK + cc4]);
    }
#pragma unroll
    for (int p = 0; p < 8; p++) {
        int row = crow + 16 * p;
        cp16(buf_base[0] + 4u * (uint32_t)(row * SKS + cc4), &Kb[row * DK + cc4]);
    }
    CP_COMMIT();
    CP_WAIT0();
    __syncthreads();

    // Preload Q fragments (raw bits; g_Q already tf32-rounded)
    uint32_t aq[2][8][4];
#pragma unroll
    for (int mt = 0; mt < 2; mt++)
#pragma unroll
        for (int ks = 0; ks < 8; ks++)
            ldsm_x4(aq[mt][ks], sQ_base + 4u * (uint32_t)((mt * 16 + lrow) * SQS + ks * 8 + lkc));

    // ---- Scores: S = (Q K^T)/8, double-buffered K tiles ----
    for (int kt = 0; kt < 8; kt++) {
        // issue next tile: K[kt+1], or V[0] on the last iteration
        {
            const float* src = (kt < 7) ? &Kb[(kt + 1) * 128 * DK] : &Vb[0];
            uint32_t nb = buf_base[(kt + 1) & 1];
#pragma unroll
            for (int p = 0; p < 8; p++) {
                int row = crow + 16 * p;
                cp16(nb + 4u * (uint32_t)(row * SKS + cc4), &src[row * DK + cc4]);
            }
            CP_COMMIT();
        }

        const float* kb = buf_ptr[kt & 1];
        float c[2][2][4];
#pragma unroll
        for (int mt = 0; mt < 2; mt++)
#pragma unroll
            for (int nt = 0; nt < 2; nt++)
#pragma unroll
                for (int i = 0; i < 4; i++) c[mt][nt][i] = 0.0f;

#pragma unroll
        for (int ks = 0; ks < 8; ks++) {
            uint32_t bfr[2][2];
#pragma unroll
            for (int nt = 0; nt < 2; nt++) {
                int ncol = warp * 16 + nt * 8 + (lane >> 2);
                int krow = ks * 8 + (lane & 3);
                bfr[nt][0] = __float_as_uint(kb[ncol * SKS + krow]);
                bfr[nt][1] = __float_as_uint(kb[ncol * SKS + krow + 4]);
            }
#pragma unroll
            for (int mt = 0; mt < 2; mt++)
#pragma unroll
                for (int nt = 0; nt < 2; nt++)
                    mma_tf32(c[mt][nt], aq[mt][ks], bfr[nt]);
        }
#pragma unroll
        for (int mt = 0; mt < 2; mt++) {
            int r = mt * 16 + (lane >> 2);
#pragma unroll
            for (int nt = 0; nt < 2; nt++) {
                int col = kt * 128 + warp * 16 + nt * 8 + 2 * (lane & 3);
                *(float2*)&sS[r * SSS + col] =
                    make_float2(c[mt][nt][0] * 0.125f, c[mt][nt][1] * 0.125f);
                *(float2*)&sS[(r + 8) * SSS + col] =
                    make_float2(c[mt][nt][2] * 0.125f, c[mt][nt][3] * 0.125f);
            }
        }

        CP_WAIT0();
        __syncthreads();   // next buffer ready; sS tile writes visible at loop end
    }

    // ---- Softmax per row (warp owns 4 rows); raw P -> gmem, tf32 P -> smem ----
#pragma unroll
    for (int rr = 0; rr < 4; rr++) {
        int r = warp * 4 + rr;
        float* row = sS + r * SSS;
        float mx = -3.0e38f;
#pragma unroll
        for (int k = 0; k < 8; k++) {
            float4 v = *(const float4*)&row[lane * 4 + 128 * k];
            mx = fmaxf(mx, fmaxf(fmaxf(v.x, v.y), fmaxf(v.z, v.w)));
        }
#pragma unroll
        for (int o = 16; o > 0; o >>= 1) mx = fmaxf(mx, __shfl_xor_sync(0xffffffffu, mx, o));
        float sum = 0.0f;
        float4 e[8];
#pragma unroll
        for (int k = 0; k < 8; k++) {
            float4 v = *(const float4*)&row[lane * 4 + 128 * k];
            e[k].x = __expf(v.x - mx); e[k].y = __expf(v.y - mx);
            e[k].z = __expf(v.z - mx); e[k].w = __expf(v.w - mx);
            sum += e[k].x + e[k].y + e[k].z + e[k].w;
        }
#pragma unroll
        for (int o = 16; o > 0; o >>= 1) sum += __shfl_xor_sync(0xffffffffu, sum, o);
        float inv = 1.0f / sum;
        float* arow = attn_out + ((size_t)(b * NH + h) * SS + qt * 32 + r) * SS;
#pragma unroll
        for (int k = 0; k < 8; k++) {
            float4 p = make_float4(e[k].x * inv, e[k].y * inv, e[k].z * inv, e[k].w * inv);
            *(float4*)&arow[lane * 4 + 128 * k] = p;
            float4 pr = make_float4(rnd_tf32(p.x), rnd_tf32(p.y),
                                    rnd_tf32(p.z), rnd_tf32(p.w));
            *(float4*)&row[lane * 4 + 128 * k] = pr;
        }
    }
    __syncthreads();   // all P writes visible before PV ldsm

    // ---- PV: context = P @ V, double-buffered V tiles (V0 already in flight) ----
    float acc2[2][4];
#pragma unroll
    for (int mt = 0; mt < 2; mt++)
#pragma unroll
        for (int i = 0; i < 4; i++) acc2[mt][i] = 0.0f;

    for (int vt = 0; vt < 8; vt++) {
        if (vt == 0) { CP_WAIT0(); __syncthreads(); }   // V0 ready
        if (vt < 7) {
            const float* src = &Vb[(vt + 1) * 128 * DV];
            uint32_t nb = buf_base[(vt + 1) & 1];
#pragma unroll
            for (int p = 0; p < 8; p++) {
                int row = crow + 16 * p;
                cp16(nb + 4u * (uint32_t)(row * SKS + cc4), &src[row * DV + cc4]);
            }
            CP_COMMIT();
        }

        const float* vb = buf_ptr[vt & 1];
#pragma unroll
        for (int ks = 0; ks < 16; ks++) {
            uint32_t ap[2][4];
#pragma unroll
            for (int mt = 0; mt < 2; mt++)
                ldsm_x4(ap[mt], sS_base +
                        4u * (uint32_t)((mt * 16 + lrow) * SSS + vt * 128 + ks * 8 + lkc));
            uint32_t bfr[2];
            {
                int ncol = warp * 8 + (lane >> 2);
                int krow = ks * 8 + (lane & 3);
                bfr[0] = __float_as_uint(vb[krow * SKS + ncol]);
                bfr[1] = __float_as_uint(vb[(krow + 4) * SKS + ncol]);
            }
            mma_tf32(acc2[0], ap[0], bfr);
            mma_tf32(acc2[1], ap[1], bfr);
        }

        if (vt < 7) { CP_WAIT0(); __syncthreads(); }
    }

    // Write context in [b, s, h*64 + d]
#pragma unroll
    for (int mt = 0; mt < 2; mt++) {
        int r = qt * 32 + mt * 16 + (lane >> 2);
        int col = h * DV + warp * 8 + 2 * (lane & 3);
        *(float2*)&ctx_out[((size_t)b * SS + r) * (NH * DV) + col] =
            make_float2(acc2[mt][0], acc2[mt][1]);
        *(float2*)&ctx_out[((size_t)b * SS + r + 8) * (NH * DV) + col] =
            make_float2(acc2[mt][2], acc2[mt][3]);
    }
}

// ---------------------------------------------------------------------------
// Launch
// ---------------------------------------------------------------------------
extern "C" void kernel_launch(void* const* d_in, const int* in_sizes, int n_in,
                              void* d_out, int out_size)
{
    const float* q  = (const float*)d_in[0];
    const float* k  = (const float*)d_in[1];
    const float* v  = (const float*)d_in[2];
    const float* wq = (const float*)d_in[3];
    const float* wk = (const float*)d_in[4];
    const float* wv = (const float*)d_in[5];
    const float* bq = (const float*)d_in[6];
    const float* bk = (const float*)d_in[7];
    const float* bv = (const float*)d_in[8];
    // d_in[9] = attn_mask (falsy) -> no masking

    float* ctx  = (float*)d_out;
    float* attn = (float*)d_out + (size_t)BB * SS * NH * DV;

    (void)cudaFuncSetAttribute(attn_kernel,
                               cudaFuncAttributeMaxDynamicSharedMemorySize,
                               ATTN_SMEM_BYTES);

    dim3 pgrid(DM / 128, (BB * SS) / 128, 3);
    proj_mma_kernel<<<pgrid, 256>>>(q, k, v, wq, wk, wv, bq, bk, bv);

    dim3 agrid(SS / 32, NH, BB);
    attn_kernel<<<agrid, 256, ATTN_SMEM_BYTES>>>(ctx, attn);
}